// round 14
// baseline (speedup 1.0000x reference)
#include <cuda_runtime.h>
#include <cuda_fp16.h>

// ContinuousEmbedding via trig factorization + fp16 tables + half2 combine:
//   w_j = 0.5 + 0.5*cos(a)cos(j*pi/4) + 0.5*sin(a)sin(j*pi/4), a=(pi/4)(t+3)
//   out[x] = c0*A0[pbi] + c1*A1[pbi] + c2*A2[pbi]
//
// R13: R12 two-kernel scheme (builder writes fp16 A-tables to __device__
// global once; main kernel block-copies 48KB into smem) + PDL overlap:
// builder fires cudaTriggerProgrammaticLaunchCompletion(), main kernel is
// launched with programmaticStreamSerializationAllowed and grid-syncs only
// right before reading g_tbl -> builder + launch gap hidden under main-
// kernel ramp-up. Hot loop unchanged (at the DRAM write-drain floor).

#define NUM_POINTS 64
#define OUT_DIMS   128
#define V4_PER_ROW (OUT_DIMS / 4)     // 32
#define NPBI       64                 // pbi = pb+3 in [0,63] (pb in [-3,60])
#define ROW_BYTES  256                // 128 dims * 2B fp16
#define PBI_STRIDE 768                // 3 tables * 256B
#define TBL_BYTES  (NPBI * PBI_STRIDE)        // 49,152
#define TBL_U4     (TBL_BYTES / 16)           // 3,072 uint4
#define WARPS_PB   16                 // 512 threads
#define STAGE_BYTES (WARPS_PB * 32 * 16)      // 8,192
#define SMEM_BYTES (TBL_BYTES + STAGE_BYTES)  // 57,344
#define RSQ2       0.70710678118654752440f
#define BLOCK      512

__device__ __align__(16) unsigned char g_tbl[TBL_BYTES];

extern __shared__ unsigned char s_raw[];

// ---- builder: one block per pbi, one thread per 4-dim chunk ----
__global__ void ce_build_tbl(const float* __restrict__ emb)
{
    const float cj[8] = {1.f,  RSQ2, 0.f, -RSQ2, -1.f, -RSQ2,  0.f,  RSQ2};
    const float sj[8] = {0.f,  RSQ2, 1.f,  RSQ2,  0.f, -RSQ2, -1.f, -RSQ2};

    const int pbi = blockIdx.x;        // 0..63
    const int ch  = threadIdx.x;       // 0..31
    const int pb  = pbi - 3;

    const float4* __restrict__ emb4 = reinterpret_cast<const float4*>(emb);

    float4 a0 = make_float4(0.f,0.f,0.f,0.f);
    float4 a1 = a0, a2 = a0;
    #pragma unroll
    for (int j = 0; j < 8; ++j) {
        const int p = pb + j;
        if (p >= 0 && p < NUM_POINTS) {
            const float4 e = __ldg(&emb4[p * V4_PER_ROW + ch]);
            a0.x += e.x; a0.y += e.y; a0.z += e.z; a0.w += e.w;
            a1.x = fmaf(cj[j], e.x, a1.x); a1.y = fmaf(cj[j], e.y, a1.y);
            a1.z = fmaf(cj[j], e.z, a1.z); a1.w = fmaf(cj[j], e.w, a1.w);
            a2.x = fmaf(sj[j], e.x, a2.x); a2.y = fmaf(sj[j], e.y, a2.y);
            a2.z = fmaf(sj[j], e.z, a2.z); a2.w = fmaf(sj[j], e.w, a2.w);
        }
    }
    unsigned char* base = g_tbl + pbi * PBI_STRIDE + ch * 8;
    __half2* d0 = reinterpret_cast<__half2*>(base);
    __half2* d1 = reinterpret_cast<__half2*>(base + ROW_BYTES);
    __half2* d2 = reinterpret_cast<__half2*>(base + 2 * ROW_BYTES);
    d0[0] = __floats2half2_rn(a0.x, a0.y);
    d0[1] = __floats2half2_rn(a0.z, a0.w);
    d1[0] = __floats2half2_rn(a1.x, a1.y);
    d1[1] = __floats2half2_rn(a1.z, a1.w);
    d2[0] = __floats2half2_rn(a2.x, a2.y);
    d2[1] = __floats2half2_rn(a2.z, a2.w);

    // PDL: signal that this block's contribution to g_tbl is done.
    cudaTriggerProgrammaticLaunchCompletion();
}

__global__ __launch_bounds__(BLOCK, 3)
void ContinuousEmbedding_89412629168402_kernel(const float* __restrict__ x,
                                               float* __restrict__ out,
                                               int n_x)
{
    // PDL: wait for the builder's writes to g_tbl to be visible.
    cudaGridDependencySynchronize();

    // ---- prologue: straight copy of the prebuilt table into smem ----
    {
        const uint4* __restrict__ src = reinterpret_cast<const uint4*>(g_tbl);
        uint4* dst = reinterpret_cast<uint4*>(s_raw);
        #pragma unroll
        for (int i = threadIdx.x; i < TBL_U4; i += BLOCK)
            dst[i] = __ldg(&src[i]);
    }
    __syncthreads();

    const int lane    = threadIdx.x & 31;
    const int wl      = threadIdx.x >> 5;
    const int wid_g   = blockIdx.x * WARPS_PB + wl;
    const int w_total = gridDim.x * WARPS_PB;
    const int n_tiles = (n_x + 31) >> 5;

    float4* stage = reinterpret_cast<float4*>(s_raw + TBL_BYTES) + wl * 32;
    float4* __restrict__ out4 = reinterpret_cast<float4*>(out);

    const float cj[8] = {1.f,  RSQ2, 0.f, -RSQ2, -1.f, -RSQ2,  0.f,  RSQ2};
    const float sj[8] = {0.f,  RSQ2, 1.f,  RSQ2,  0.f, -RSQ2, -1.f, -RSQ2};

    for (int wt = wid_g; wt < n_tiles; wt += w_total) {
        const int base = wt << 5;

        // ---- per-lane precompute for this lane's x ----
        const int xi = base + lane;
        const float xv = (xi < n_x) ? x[xi] : 0.f;
        const float xs = (xv + 1.0f) * 32.0f;
        const float f  = floorf(xs);
        const int   pb = (int)f - 3;
        const float t  = xs - f;
        const float a  = 0.78539816339744830962f * (t + 3.0f);
        const float ca = __cosf(a);
        const float sa = __sinf(a);

        float n0 = 0.f, n1 = 0.f, n2 = 0.f;
        #pragma unroll
        for (int j = 0; j < 8; ++j) {
            const int p = pb + j;
            if (p >= 0 && p < NUM_POINTS) { n0 += 1.f; n1 += cj[j]; n2 += sj[j]; }
        }
        const float s   = 0.5f * (n0 + ca * n1 + sa * n2);
        const float inv = (s > 0.f) ? (1.0f / s) : 0.f;
        int pbi = pb + 3;
        pbi = max(0, min(NPBI - 1, pbi));

        const __half2 h0  = __float2half2_rn(0.5f * inv);
        const __half2 h1  = __float2half2_rn(0.5f * ca * inv);
        const __half2 h2c = __float2half2_rn(0.5f * sa * inv);

        float4 cf;
        cf.x = __uint_as_float(*reinterpret_cast<const unsigned int*>(&h0));
        cf.y = __uint_as_float(*reinterpret_cast<const unsigned int*>(&h1));
        cf.z = __uint_as_float(*reinterpret_cast<const unsigned int*>(&h2c));
        cf.w = __int_as_float(pbi * PBI_STRIDE);

        __syncwarp();                 // previous tile's readers are done
        stage[lane] = cf;
        __syncwarp();                 // staging visible to all lanes

        // ---- broadcast loop: one x per k ----
        const int cnt = min(32, n_x - base);
        for (int k = 0; k < cnt; ++k) {
            const float4 c = stage[k];               // broadcast LDS.128
            const unsigned int b0 = __float_as_uint(c.x);
            const unsigned int b1 = __float_as_uint(c.y);
            const unsigned int b2 = __float_as_uint(c.z);
            const __half2 C0 = *reinterpret_cast<const __half2*>(&b0);
            const __half2 C1 = *reinterpret_cast<const __half2*>(&b1);
            const __half2 C2 = *reinterpret_cast<const __half2*>(&b2);

            const unsigned char* row = s_raw + __float_as_int(c.w) + lane * 8;
            const uint2 u0 = *reinterpret_cast<const uint2*>(row);
            const uint2 u1 = *reinterpret_cast<const uint2*>(row + ROW_BYTES);
            const uint2 u2 = *reinterpret_cast<const uint2*>(row + 2 * ROW_BYTES);

            const __half2 A0l = *reinterpret_cast<const __half2*>(&u0.x);
            const __half2 A0h = *reinterpret_cast<const __half2*>(&u0.y);
            const __half2 A1l = *reinterpret_cast<const __half2*>(&u1.x);
            const __half2 A1h = *reinterpret_cast<const __half2*>(&u1.y);
            const __half2 A2l = *reinterpret_cast<const __half2*>(&u2.x);
            const __half2 A2h = *reinterpret_cast<const __half2*>(&u2.y);

            const __half2 accl = __hfma2(A2l, C2, __hfma2(A1l, C1, __hmul2(A0l, C0)));
            const __half2 acch = __hfma2(A2h, C2, __hfma2(A1h, C1, __hmul2(A0h, C0)));

            const float2 lo = __half22float2(accl);
            const float2 hi = __half22float2(acch);
            float4 acc;
            acc.x = lo.x; acc.y = lo.y; acc.z = hi.x; acc.w = hi.y;

            __stcs(&out4[(size_t)(base + k) * V4_PER_ROW + lane], acc);
        }
    }
}

extern "C" void kernel_launch(void* const* d_in, const int* in_sizes, int n_in,
                              void* d_out, int out_size)
{
    const float* x   = (const float*)d_in[0];   // [64, 8192] f32
    const float* emb = (const float*)d_in[1];   // [64, 128]  f32
    float* out = (float*)d_out;                 // [64, 8192, 128] f32

    const int n_x = in_sizes[0];                // 524288

    static bool attr_set = false;
    if (!attr_set) {
        cudaFuncSetAttribute(ContinuousEmbedding_89412629168402_kernel,
                             cudaFuncAttributeMaxDynamicSharedMemorySize,
                             SMEM_BYTES);
        attr_set = true;
    }

    // 1) build the 48KB fp16 table once (64 blocks x 32 threads)
    ce_build_tbl<<<NPBI, 32>>>(emb);

    // 2) main kernel, PDL-overlapped with the builder:
    //    CTAs launch + ramp up while the builder finishes; each CTA
    //    grid-syncs right before reading g_tbl.
    cudaLaunchConfig_t cfg = {};
    cfg.gridDim  = dim3(456, 1, 1);    // 3 CTAs/SM * ~152 SMs
    cfg.blockDim = dim3(BLOCK, 1, 1);
    cfg.dynamicSmemBytes = SMEM_BYTES;
    cfg.stream = 0;
    cudaLaunchAttribute attrs[1];
    attrs[0].id = cudaLaunchAttributeProgrammaticStreamSerialization;
    attrs[0].val.programmaticStreamSerializationAllowed = 1;
    cfg.attrs = attrs;
    cfg.numAttrs = 1;
    cudaLaunchKernelEx(&cfg, ContinuousEmbedding_89412629168402_kernel,
                       x, out, n_x);
}

// round 15
// speedup vs baseline: 1.2389x; 1.2389x over previous
#include <cuda_runtime.h>
#include <cuda_fp16.h>

// ContinuousEmbedding via trig factorization + fp16 tables + half2 combine:
//   w_j = 0.5 + 0.5*cos(a)cos(j*pi/4) + 0.5*sin(a)sin(j*pi/4), a=(pi/4)(t+3)
//   out[x] = c0*A0[pbi] + c1*A1[pbi] + c2*A2[pbi]
//
// R14: single kernel (PDL + two-kernel schemes both regressed on wall).
// Cheap prologue: each thread builds 4 CONSECUTIVE pbi entries for its
// dim-chunk via an 11-row sliding register window -> 11 batched LDG.128
// instead of 32 scattered masked ones. Hot loop = verified R7/R8 body
// (at the DRAM write-drain floor, ncu 46.0 with a copy-prologue).

#define NUM_POINTS 64
#define OUT_DIMS   128
#define V4_PER_ROW (OUT_DIMS / 4)     // 32
#define NPBI       64                 // pbi = pb+3 in [0,63] (pb in [-3,60])
#define ROW_BYTES  256                // 128 dims * 2B fp16
#define PBI_STRIDE 768                // 3 tables * 256B
#define TBL_BYTES  (NPBI * PBI_STRIDE)        // 49,152
#define WARPS_PB   16                 // 512 threads
#define STAGE_BYTES (WARPS_PB * 32 * 16)      // 8,192
#define SMEM_BYTES (TBL_BYTES + STAGE_BYTES)  // 57,344
#define RSQ2       0.70710678118654752440f
#define BLOCK      512

extern __shared__ unsigned char s_raw[];

__global__ __launch_bounds__(BLOCK, 3)
void ContinuousEmbedding_89412629168402_kernel(const float* __restrict__ x,
                                               const float* __restrict__ emb,
                                               float* __restrict__ out,
                                               int n_x)
{
    const float cj[8] = {1.f,  RSQ2, 0.f, -RSQ2, -1.f, -RSQ2,  0.f,  RSQ2};
    const float sj[8] = {0.f,  RSQ2, 1.f,  RSQ2,  0.f, -RSQ2, -1.f, -RSQ2};

    // ---- prologue: build fp16 A0/A1/A2 tables, sliding-window variant ----
    // Thread t: dim-chunk ch = t&31, pbi group g = t>>5 -> pbi in [4g, 4g+3].
    // Entries for pbi=P need rows P-3..P+4; the 4 entries together need the
    // 11-row window [4g-3, 4g+7]. Out-of-grid rows load as zero (== masking).
    {
        const float4* __restrict__ emb4 = reinterpret_cast<const float4*>(emb);
        const int ch = threadIdx.x & 31;
        const int g  = threadIdx.x >> 5;        // 0..15
        const int r0 = 4 * g - 3;               // first row of the window

        float4 r[11];
        #pragma unroll
        for (int i = 0; i < 11; ++i) {
            const int row = r0 + i;
            if (row >= 0 && row < NUM_POINTS)
                r[i] = __ldg(&emb4[row * V4_PER_ROW + ch]);
            else
                r[i] = make_float4(0.f, 0.f, 0.f, 0.f);
        }

        #pragma unroll
        for (int e = 0; e < 4; ++e) {
            const int pbi = 4 * g + e;
            float4 a0 = make_float4(0.f,0.f,0.f,0.f);
            float4 a1 = a0, a2 = a0;
            #pragma unroll
            for (int j = 0; j < 8; ++j) {
                const float4 v = r[e + j];
                a0.x += v.x; a0.y += v.y; a0.z += v.z; a0.w += v.w;
                a1.x = fmaf(cj[j], v.x, a1.x); a1.y = fmaf(cj[j], v.y, a1.y);
                a1.z = fmaf(cj[j], v.z, a1.z); a1.w = fmaf(cj[j], v.w, a1.w);
                a2.x = fmaf(sj[j], v.x, a2.x); a2.y = fmaf(sj[j], v.y, a2.y);
                a2.z = fmaf(sj[j], v.z, a2.z); a2.w = fmaf(sj[j], v.w, a2.w);
            }
            unsigned char* base = s_raw + pbi * PBI_STRIDE + ch * 8;
            __half2* d0 = reinterpret_cast<__half2*>(base);
            __half2* d1 = reinterpret_cast<__half2*>(base + ROW_BYTES);
            __half2* d2 = reinterpret_cast<__half2*>(base + 2 * ROW_BYTES);
            d0[0] = __floats2half2_rn(a0.x, a0.y);
            d0[1] = __floats2half2_rn(a0.z, a0.w);
            d1[0] = __floats2half2_rn(a1.x, a1.y);
            d1[1] = __floats2half2_rn(a1.z, a1.w);
            d2[0] = __floats2half2_rn(a2.x, a2.y);
            d2[1] = __floats2half2_rn(a2.z, a2.w);
        }
    }
    __syncthreads();

    const int lane    = threadIdx.x & 31;
    const int wl      = threadIdx.x >> 5;
    const int wid_g   = blockIdx.x * WARPS_PB + wl;
    const int w_total = gridDim.x * WARPS_PB;
    const int n_tiles = (n_x + 31) >> 5;

    float4* stage = reinterpret_cast<float4*>(s_raw + TBL_BYTES) + wl * 32;
    float4* __restrict__ out4 = reinterpret_cast<float4*>(out);

    for (int wt = wid_g; wt < n_tiles; wt += w_total) {
        const int base = wt << 5;

        // ---- per-lane precompute for this lane's x ----
        const int xi = base + lane;
        const float xv = (xi < n_x) ? x[xi] : 0.f;
        const float xs = (xv + 1.0f) * 32.0f;
        const float f  = floorf(xs);
        const int   pb = (int)f - 3;
        const float t  = xs - f;
        const float a  = 0.78539816339744830962f * (t + 3.0f);
        const float ca = __cosf(a);
        const float sa = __sinf(a);

        float n0 = 0.f, n1 = 0.f, n2 = 0.f;
        #pragma unroll
        for (int j = 0; j < 8; ++j) {
            const int p = pb + j;
            if (p >= 0 && p < NUM_POINTS) { n0 += 1.f; n1 += cj[j]; n2 += sj[j]; }
        }
        const float s   = 0.5f * (n0 + ca * n1 + sa * n2);
        const float inv = (s > 0.f) ? (1.0f / s) : 0.f;
        int pbi = pb + 3;
        pbi = max(0, min(NPBI - 1, pbi));

        const __half2 h0  = __float2half2_rn(0.5f * inv);
        const __half2 h1  = __float2half2_rn(0.5f * ca * inv);
        const __half2 h2c = __float2half2_rn(0.5f * sa * inv);

        float4 cf;
        cf.x = __uint_as_float(*reinterpret_cast<const unsigned int*>(&h0));
        cf.y = __uint_as_float(*reinterpret_cast<const unsigned int*>(&h1));
        cf.z = __uint_as_float(*reinterpret_cast<const unsigned int*>(&h2c));
        cf.w = __int_as_float(pbi * PBI_STRIDE);

        __syncwarp();                 // previous tile's readers are done
        stage[lane] = cf;
        __syncwarp();                 // staging visible to all lanes

        // ---- broadcast loop: one x per k ----
        const int cnt = min(32, n_x - base);
        for (int k = 0; k < cnt; ++k) {
            const float4 c = stage[k];               // broadcast LDS.128
            const unsigned int b0 = __float_as_uint(c.x);
            const unsigned int b1 = __float_as_uint(c.y);
            const unsigned int b2 = __float_as_uint(c.z);
            const __half2 C0 = *reinterpret_cast<const __half2*>(&b0);
            const __half2 C1 = *reinterpret_cast<const __half2*>(&b1);
            const __half2 C2 = *reinterpret_cast<const __half2*>(&b2);

            const unsigned char* row = s_raw + __float_as_int(c.w) + lane * 8;
            const uint2 u0 = *reinterpret_cast<const uint2*>(row);
            const uint2 u1 = *reinterpret_cast<const uint2*>(row + ROW_BYTES);
            const uint2 u2 = *reinterpret_cast<const uint2*>(row + 2 * ROW_BYTES);

            const __half2 A0l = *reinterpret_cast<const __half2*>(&u0.x);
            const __half2 A0h = *reinterpret_cast<const __half2*>(&u0.y);
            const __half2 A1l = *reinterpret_cast<const __half2*>(&u1.x);
            const __half2 A1h = *reinterpret_cast<const __half2*>(&u1.y);
            const __half2 A2l = *reinterpret_cast<const __half2*>(&u2.x);
            const __half2 A2h = *reinterpret_cast<const __half2*>(&u2.y);

            const __half2 accl = __hfma2(A2l, C2, __hfma2(A1l, C1, __hmul2(A0l, C0)));
            const __half2 acch = __hfma2(A2h, C2, __hfma2(A1h, C1, __hmul2(A0h, C0)));

            const float2 lo = __half22float2(accl);
            const float2 hi = __half22float2(acch);
            float4 acc;
            acc.x = lo.x; acc.y = lo.y; acc.z = hi.x; acc.w = hi.y;

            __stcs(&out4[(size_t)(base + k) * V4_PER_ROW + lane], acc);
        }
    }
}

extern "C" void kernel_launch(void* const* d_in, const int* in_sizes, int n_in,
                              void* d_out, int out_size)
{
    const float* x   = (const float*)d_in[0];   // [64, 8192] f32
    const float* emb = (const float*)d_in[1];   // [64, 128]  f32
    float* out = (float*)d_out;                 // [64, 8192, 128] f32

    const int n_x = in_sizes[0];                // 524288

    static bool attr_set = false;
    if (!attr_set) {
        cudaFuncSetAttribute(ContinuousEmbedding_89412629168402_kernel,
                             cudaFuncAttributeMaxDynamicSharedMemorySize,
                             SMEM_BYTES);
        attr_set = true;
    }

    // 3 CTAs/SM * ~152 SMs, grid-stride over 32-x tiles
    const int blocks = 456;
    ContinuousEmbedding_89412629168402_kernel<<<blocks, BLOCK, SMEM_BYTES>>>(
        x, emb, out, n_x);
}

// round 16
// speedup vs baseline: 1.3299x; 1.0735x over previous
#include <cuda_runtime.h>
#include <cuda_fp16.h>

// ContinuousEmbedding via trig factorization + fp16 tables + half2 combine:
//   w_j = 0.5 + 0.5*cos(a)cos(j*pi/4) + 0.5*sin(a)sin(j*pi/4), a=(pi/4)(t+3)
//   out[x] = c0*A0[pbi] + c1*A1[pbi] + c2*A2[pbi]
// A0/A1/A2 per-block in shared as __half (zero-masked rows outside grid ->
// exact boundary handling). Per x: 1 broadcast LDS.128 + 3 LDS.64 + STG.128.
//
// FINAL (locked R7 config): 15 rounds established this kernel sits at the
// DRAM write-drain floor for the 256MB fp32 output (~4.5TB/s effective).
// Verified-best wall: 49.2us (from 86.1us baseline). Variations in
// occupancy, issue count, MLP, work distribution, store width, prologue
// structure, and kernel splitting were all flat or regressions.

#define NUM_POINTS 64
#define OUT_DIMS   128
#define V4_PER_ROW (OUT_DIMS / 4)     // 32
#define NPBI       64                 // pbi = pb+3 in [0,63] (pb in [-3,60])
#define ROW_BYTES  256                // 128 dims * 2B fp16
#define PBI_STRIDE 768                // 3 tables * 256B
#define TBL_BYTES  (NPBI * PBI_STRIDE)        // 49,152
#define WARPS_PB   16                 // 512 threads
#define STAGE_BYTES (WARPS_PB * 32 * 16)      // 8,192
#define SMEM_BYTES (TBL_BYTES + STAGE_BYTES)  // 57,344
#define RSQ2       0.70710678118654752440f
#define BLOCK      512

extern __shared__ unsigned char s_raw[];

__global__ __launch_bounds__(BLOCK, 3)
void ContinuousEmbedding_89412629168402_kernel(const float* __restrict__ x,
                                               const float* __restrict__ emb,
                                               float* __restrict__ out,
                                               int n_x)
{
    // ---- build fp16 A0/A1/A2 tables (once per block) ----
    const float4* __restrict__ emb4 = reinterpret_cast<const float4*>(emb);
    {
        const float cj[8] = {1.f,  RSQ2, 0.f, -RSQ2, -1.f, -RSQ2,  0.f,  RSQ2};
        const float sj[8] = {0.f,  RSQ2, 1.f,  RSQ2,  0.f, -RSQ2, -1.f, -RSQ2};
        for (int tr = threadIdx.x; tr < NPBI * V4_PER_ROW; tr += BLOCK) {
            const int pbi = tr >> 5;
            const int ch  = tr & 31;
            const int pb  = pbi - 3;
            float4 a0 = make_float4(0.f,0.f,0.f,0.f);
            float4 a1 = a0, a2 = a0;
            #pragma unroll
            for (int j = 0; j < 8; ++j) {
                const int p = pb + j;
                if (p >= 0 && p < NUM_POINTS) {
                    const float4 e = __ldg(&emb4[p * V4_PER_ROW + ch]);
                    a0.x += e.x; a0.y += e.y; a0.z += e.z; a0.w += e.w;
                    a1.x = fmaf(cj[j], e.x, a1.x); a1.y = fmaf(cj[j], e.y, a1.y);
                    a1.z = fmaf(cj[j], e.z, a1.z); a1.w = fmaf(cj[j], e.w, a1.w);
                    a2.x = fmaf(sj[j], e.x, a2.x); a2.y = fmaf(sj[j], e.y, a2.y);
                    a2.z = fmaf(sj[j], e.z, a2.z); a2.w = fmaf(sj[j], e.w, a2.w);
                }
            }
            unsigned char* base = s_raw + pbi * PBI_STRIDE + ch * 8;
            __half2* d0 = reinterpret_cast<__half2*>(base);
            __half2* d1 = reinterpret_cast<__half2*>(base + ROW_BYTES);
            __half2* d2 = reinterpret_cast<__half2*>(base + 2 * ROW_BYTES);
            d0[0] = __floats2half2_rn(a0.x, a0.y);
            d0[1] = __floats2half2_rn(a0.z, a0.w);
            d1[0] = __floats2half2_rn(a1.x, a1.y);
            d1[1] = __floats2half2_rn(a1.z, a1.w);
            d2[0] = __floats2half2_rn(a2.x, a2.y);
            d2[1] = __floats2half2_rn(a2.z, a2.w);
        }
    }
    __syncthreads();

    const int lane    = threadIdx.x & 31;
    const int wl      = threadIdx.x >> 5;
    const int wid_g   = blockIdx.x * WARPS_PB + wl;
    const int w_total = gridDim.x * WARPS_PB;
    const int n_tiles = (n_x + 31) >> 5;

    float4* stage = reinterpret_cast<float4*>(s_raw + TBL_BYTES) + wl * 32;
    float4* __restrict__ out4 = reinterpret_cast<float4*>(out);

    const float cj[8] = {1.f,  RSQ2, 0.f, -RSQ2, -1.f, -RSQ2,  0.f,  RSQ2};
    const float sj[8] = {0.f,  RSQ2, 1.f,  RSQ2,  0.f, -RSQ2, -1.f, -RSQ2};

    for (int wt = wid_g; wt < n_tiles; wt += w_total) {
        const int base = wt << 5;

        // ---- per-lane precompute for this lane's x ----
        const int xi = base + lane;
        const float xv = (xi < n_x) ? x[xi] : 0.f;
        const float xs = (xv + 1.0f) * 32.0f;
        const float f  = floorf(xs);
        const int   pb = (int)f - 3;
        const float t  = xs - f;
        const float a  = 0.78539816339744830962f * (t + 3.0f);
        const float ca = __cosf(a);
        const float sa = __sinf(a);

        float n0 = 0.f, n1 = 0.f, n2 = 0.f;
        #pragma unroll
        for (int j = 0; j < 8; ++j) {
            const int p = pb + j;
            if (p >= 0 && p < NUM_POINTS) { n0 += 1.f; n1 += cj[j]; n2 += sj[j]; }
        }
        const float s   = 0.5f * (n0 + ca * n1 + sa * n2);
        const float inv = (s > 0.f) ? (1.0f / s) : 0.f;
        int pbi = pb + 3;
        pbi = max(0, min(NPBI - 1, pbi));

        // coeffs as duplicated half2 (bits stashed in float4 stage)
        const __half2 h0  = __float2half2_rn(0.5f * inv);
        const __half2 h1  = __float2half2_rn(0.5f * ca * inv);
        const __half2 h2c = __float2half2_rn(0.5f * sa * inv);

        float4 cf;
        cf.x = __uint_as_float(*reinterpret_cast<const unsigned int*>(&h0));
        cf.y = __uint_as_float(*reinterpret_cast<const unsigned int*>(&h1));
        cf.z = __uint_as_float(*reinterpret_cast<const unsigned int*>(&h2c));
        cf.w = __int_as_float(pbi * PBI_STRIDE);

        __syncwarp();                 // previous tile's readers are done
        stage[lane] = cf;
        __syncwarp();                 // staging visible to all lanes

        // ---- broadcast loop: one x per k ----
        const int cnt = min(32, n_x - base);
        for (int k = 0; k < cnt; ++k) {
            const float4 c = stage[k];               // broadcast LDS.128
            const unsigned int b0 = __float_as_uint(c.x);
            const unsigned int b1 = __float_as_uint(c.y);
            const unsigned int b2 = __float_as_uint(c.z);
            const __half2 C0 = *reinterpret_cast<const __half2*>(&b0);
            const __half2 C1 = *reinterpret_cast<const __half2*>(&b1);
            const __half2 C2 = *reinterpret_cast<const __half2*>(&b2);

            const unsigned char* row = s_raw + __float_as_int(c.w) + lane * 8;
            const uint2 u0 = *reinterpret_cast<const uint2*>(row);
            const uint2 u1 = *reinterpret_cast<const uint2*>(row + ROW_BYTES);
            const uint2 u2 = *reinterpret_cast<const uint2*>(row + 2 * ROW_BYTES);

            const __half2 A0l = *reinterpret_cast<const __half2*>(&u0.x);
            const __half2 A0h = *reinterpret_cast<const __half2*>(&u0.y);
            const __half2 A1l = *reinterpret_cast<const __half2*>(&u1.x);
            const __half2 A1h = *reinterpret_cast<const __half2*>(&u1.y);
            const __half2 A2l = *reinterpret_cast<const __half2*>(&u2.x);
            const __half2 A2h = *reinterpret_cast<const __half2*>(&u2.y);

            const __half2 accl = __hfma2(A2l, C2, __hfma2(A1l, C1, __hmul2(A0l, C0)));
            const __half2 acch = __hfma2(A2h, C2, __hfma2(A1h, C1, __hmul2(A0h, C0)));

            const float2 lo = __half22float2(accl);
            const float2 hi = __half22float2(acch);
            float4 acc;
            acc.x = lo.x; acc.y = lo.y; acc.z = hi.x; acc.w = hi.y;

            __stcs(&out4[(size_t)(base + k) * V4_PER_ROW + lane], acc);
        }
    }
}

extern "C" void kernel_launch(void* const* d_in, const int* in_sizes, int n_in,
                              void* d_out, int out_size)
{
    const float* x   = (const float*)d_in[0];   // [64, 8192] f32
    const float* emb = (const float*)d_in[1];   // [64, 128]  f32
    float* out = (float*)d_out;                 // [64, 8192, 128] f32

    const int n_x = in_sizes[0];                // 524288

    static bool attr_set = false;
    if (!attr_set) {
        cudaFuncSetAttribute(ContinuousEmbedding_89412629168402_kernel,
                             cudaFuncAttributeMaxDynamicSharedMemorySize,
                             SMEM_BYTES);
        attr_set = true;
    }

    // 3 CTAs/SM * ~152 SMs, grid-stride over 32-x tiles (verified-best config)
    const int blocks = 456;
    ContinuousEmbedding_89412629168402_kernel<<<blocks, BLOCK, SMEM_BYTES>>>(
        x, emb, out, n_x);
}